// round 7
// baseline (speedup 1.0000x reference)
#include <cuda_runtime.h>
#include <cuda_fp16.h>
#include <cstdint>

// Problem constants
#define CTXD   512
#define HIDD   2048
#define NCELLS 4096      // 64*64
#define NBATCH 8
#define KNN    8
#define MTOT   (NBATCH * NCELLS)   // 32768

// Scratch (allowed: __device__ globals)
__device__ __half g_aggh[(size_t)MTOT * CTXD];  // 32 MB fp16 agg
__device__ __half g_Wh[(size_t)HIDD * CTXD];    // 2 MB  fp16 W^T (N rows, K cols)

// ---------------------------------------------------------------------------
// Kernel 1: fused prep: agg (4 cells/block) + W transpose->fp16
// grid: [0, 8192) agg blocks, [8192, 9216) wtrans blocks. 128 threads.
// ---------------------------------------------------------------------------
__global__ __launch_bounds__(128) void prep_kernel(
    const float* __restrict__ x,
    const int*   __restrict__ nn_idx,
    const float* __restrict__ sim,
    const float* __restrict__ W)
{
    const int bid = blockIdx.x;
    const int t   = threadIdx.x;

    if (bid < 8192) {
        // ---- agg ----
        const int n0 = (bid & 1023) * 4;
        const int b  = bid >> 10;

        __shared__ int   s_idx[4 * KNN];
        __shared__ float s_sim[4 * KNN];
        if (t < 4 * KNN) {
            s_idx[t] = nn_idx[n0 * KNN + t];
            s_sim[t] = sim[n0 * KNN + t];
        }
        __syncthreads();

        const float4* xb = reinterpret_cast<const float4*>(x) +
                           (size_t)b * NCELLS * (CTXD / 4);
        uint2* dst = reinterpret_cast<uint2*>(g_aggh);

#pragma unroll
        for (int c = 0; c < 4; c++) {
            float4 acc = make_float4(0.f, 0.f, 0.f, 0.f);
#pragma unroll
            for (int k = 0; k < KNN; k++) {
                const float  s = s_sim[c * KNN + k];
                const float4 v = xb[(size_t)s_idx[c * KNN + k] * (CTXD / 4) + t];
                acc.x = fmaf(s, v.x, acc.x);
                acc.y = fmaf(s, v.y, acc.y);
                acc.z = fmaf(s, v.z, acc.z);
                acc.w = fmaf(s, v.w, acc.w);
            }
            __half2 h0 = __float22half2_rn(make_float2(acc.x, acc.y));
            __half2 h1 = __float22half2_rn(make_float2(acc.z, acc.w));
            uint2 p;
            p.x = *reinterpret_cast<uint32_t*>(&h0);
            p.y = *reinterpret_cast<uint32_t*>(&h1);
            dst[((size_t)b * NCELLS + n0 + c) * (CTXD / 4) + t] = p;
        }
    } else {
        // ---- wtrans: Wt[n][k] = (half)W[k][n], 32x32 tile, 128 threads ----
        const int wb = bid - 8192;           // 0..1023
        const int bx = wb & 63;              // HIDD/32
        const int by = wb >> 6;              // CTXD/32
        const int tx = t & 31;
        const int ty = t >> 5;               // 0..3

        __shared__ float tile[32][33];
#pragma unroll
        for (int i = 0; i < 8; i++)
            tile[ty + i * 4][tx] =
                W[(size_t)(by * 32 + ty + i * 4) * HIDD + bx * 32 + tx];
        __syncthreads();
#pragma unroll
        for (int i = 0; i < 8; i++)
            g_Wh[(size_t)(bx * 32 + ty + i * 4) * CTXD + by * 32 + tx] =
                __float2half(tile[tx][ty + i * 4]);
    }
}

// ---------------------------------------------------------------------------
// Kernel 2: hybrid GEMM  C[M,N] = A[M,K] @ Wt[N,K]^T, fp32 accum
//   blocks [0,128):   persistent FFMA CTAs, 4 tiles each, m-blocks 224..255
//   blocks [128,3712): HMMA CTAs (round-6 code), m-blocks 0..223
// Both: 128x128 tile, BK=64, 3-stage cp.async, 128 threads, 2 CTA/SM.
// ---------------------------------------------------------------------------
#define BM 128
#define BN 128
#define BK 64
#define NT (CTXD / BK)         // 8 k-chunks
#define SSTRIDE 72             // BK + 8 pad (halves)
#define TILE_H (128 * SSTRIDE)
#define STAGE_H (2 * TILE_H)
#define GEMM_SMEM (3 * STAGE_H * 2)   // 110592 bytes

#define FMA_CTAS    128
#define FMA_TILES   4          // tiles per fma CTA
#define FMA_MBLK0   224        // fma covers m-blocks 224..255
#define TENSOR_MBLK 224        // tensor covers m-blocks 0..223

__device__ __forceinline__ void cpasync16(uint32_t saddr, const void* g) {
    asm volatile("cp.async.cg.shared.global [%0], [%1], 16;\n" :: "r"(saddr), "l"(g));
}
__device__ __forceinline__ void ldsm_x4(uint32_t& r0, uint32_t& r1,
                                        uint32_t& r2, uint32_t& r3, uint32_t a) {
    asm volatile("ldmatrix.sync.aligned.m8n8.x4.shared.b16 {%0,%1,%2,%3},[%4];"
                 : "=r"(r0), "=r"(r1), "=r"(r2), "=r"(r3) : "r"(a));
}

// shared chunk loader (A/B fp16 tiles, SSTRIDE layout)
__device__ __forceinline__ void load_chunk(
    __half* sm, int buf, int kt, int m0, int n0,
    const __half* __restrict__ A, const __half* __restrict__ B, int tid)
{
    __half* Asb = sm + buf * STAGE_H;
    __half* Bsb = Asb + TILE_H;
    const __half* Ag = A + (size_t)m0 * CTXD + kt * BK;
    const __half* Bg = B + (size_t)n0 * CTXD + kt * BK;
#pragma unroll
    for (int i = 0; i < 8; i++) {
        int idx = i * 128 + tid;
        int row = idx >> 3;
        int c8  = (idx & 7) * 8;
        cpasync16((uint32_t)__cvta_generic_to_shared(Asb + row * SSTRIDE + c8),
                  Ag + (size_t)row * CTXD + c8);
    }
#pragma unroll
    for (int i = 0; i < 8; i++) {
        int idx = i * 128 + tid;
        int row = idx >> 3;
        int c8  = (idx & 7) * 8;
        cpasync16((uint32_t)__cvta_generic_to_shared(Bsb + row * SSTRIDE + c8),
                  Bg + (size_t)row * CTXD + c8);
    }
    asm volatile("cp.async.commit_group;\n");
}

__global__ __launch_bounds__(128, 2) void gemm_hybrid(
    const __half* __restrict__ A,   // [MTOT][CTXD]
    const __half* __restrict__ B,   // [HIDD][CTXD]  (W^T)
    float*        __restrict__ C)   // [MTOT][HIDD]
{
    extern __shared__ __half sm[];
    const int tid  = threadIdx.x;
    const int bid  = blockIdx.x;

    if (bid >= FMA_CTAS) {
        // =================== HMMA path (round-6 proven code) ===============
        const int tb   = bid - FMA_CTAS;
        const int m0   = (tb >> 4) * BM;
        const int n0   = (tb & 15) * BN;
        const int lane = tid & 31;
        const int warp = tid >> 5;
        const int wm   = warp & 1;
        const int wn   = warp >> 1;
        const int g    = lane >> 2;
        const int t4   = lane & 3;

        float acc[4][8][4];
#pragma unroll
        for (int i = 0; i < 4; i++)
#pragma unroll
            for (int j = 0; j < 8; j++)
#pragma unroll
                for (int r = 0; r < 4; r++) acc[i][j][r] = 0.f;

        load_chunk(sm, 0, 0, m0, n0, A, B, tid);
        load_chunk(sm, 1, 1, m0, n0, A, B, tid);

        const int a_r  = lane & 15;
        const int a_k  = (lane >> 4) * 8;
        const int b_r  = lane & 7;
        const int b_no = ((lane >> 3) >> 1) * 8;
        const int b_ko = ((lane >> 3) & 1) * 8;

        for (int kt = 0; kt < NT; ++kt) {
            if (kt + 1 < NT) asm volatile("cp.async.wait_group 1;\n");
            else             asm volatile("cp.async.wait_group 0;\n");
            __syncthreads();
            if (kt + 2 < NT) load_chunk(sm, (kt + 2) % 3, kt + 2, m0, n0, A, B, tid);

            const __half* Asb = sm + (kt % 3) * STAGE_H;
            const __half* Bsb = Asb + TILE_H;

#pragma unroll
            for (int ks = 0; ks < 4; ++ks) {
                const int k0 = ks * 16;
                uint32_t af[4][4];
#pragma unroll
                for (int mi = 0; mi < 4; ++mi) {
                    uint32_t a = (uint32_t)__cvta_generic_to_shared(
                        Asb + (wm * 64 + mi * 16 + a_r) * SSTRIDE + k0 + a_k);
                    ldsm_x4(af[mi][0], af[mi][1], af[mi][2], af[mi][3], a);
                }
                uint32_t bf[8][2];
#pragma unroll
                for (int nj = 0; nj < 4; ++nj) {
                    uint32_t a = (uint32_t)__cvta_generic_to_shared(
                        Bsb + (wn * 64 + nj * 16 + b_no + b_r) * SSTRIDE + k0 + b_ko);
                    ldsm_x4(bf[2 * nj][0], bf[2 * nj][1],
                            bf[2 * nj + 1][0], bf[2 * nj + 1][1], a);
                }
#pragma unroll
                for (int mi = 0; mi < 4; ++mi)
#pragma unroll
                    for (int ni = 0; ni < 8; ++ni) {
                        asm volatile(
                            "mma.sync.aligned.m16n8k16.row.col.f32.f16.f16.f32 "
                            "{%0,%1,%2,%3},{%4,%5,%6,%7},{%8,%9},{%0,%1,%2,%3};\n"
                            : "+f"(acc[mi][ni][0]), "+f"(acc[mi][ni][1]),
                              "+f"(acc[mi][ni][2]), "+f"(acc[mi][ni][3])
                            : "r"(af[mi][0]), "r"(af[mi][1]),
                              "r"(af[mi][2]), "r"(af[mi][3]),
                              "r"(bf[ni][0]), "r"(bf[ni][1]));
                    }
            }
            __syncthreads();
        }

#pragma unroll
        for (int mi = 0; mi < 4; ++mi) {
#pragma unroll
            for (int ni = 0; ni < 8; ++ni) {
                const int r = m0 + wm * 64 + mi * 16 + g;
                const int c = n0 + wn * 64 + ni * 8 + t4 * 2;
                float2 v0 = make_float2(acc[mi][ni][0], acc[mi][ni][1]);
                float2 v1 = make_float2(acc[mi][ni][2], acc[mi][ni][3]);
                *reinterpret_cast<float2*>(C + (size_t)r * HIDD + c)       = v0;
                *reinterpret_cast<float2*>(C + (size_t)(r + 8) * HIDD + c) = v1;
            }
        }
    } else {
        // =================== FFMA path: 4 tiles, 8x16 per thread ===========
        const int tr = tid & 15;       // row group
        const int tc = tid >> 4;       // 0..7 col group

        for (int tile = 0; tile < FMA_TILES; ++tile) {
            const int tile_id = bid * FMA_TILES + tile;       // 0..511
            const int m0 = (FMA_MBLK0 + (tile_id >> 4)) * BM;
            const int n0 = (tile_id & 15) * BN;

            float acc[8][16];
#pragma unroll
            for (int i = 0; i < 8; i++)
#pragma unroll
                for (int j = 0; j < 16; j++) acc[i][j] = 0.f;

            load_chunk(sm, 0, 0, m0, n0, A, B, tid);
            load_chunk(sm, 1, 1, m0, n0, A, B, tid);

            for (int kt = 0; kt < NT; ++kt) {
                if (kt + 1 < NT) asm volatile("cp.async.wait_group 1;\n");
                else             asm volatile("cp.async.wait_group 0;\n");
                __syncthreads();
                if (kt + 2 < NT) load_chunk(sm, (kt + 2) % 3, kt + 2, m0, n0, A, B, tid);

                const __half* Asb = sm + (kt % 3) * STAGE_H;
                const __half* Bsb = Asb + TILE_H;

#pragma unroll 4
                for (int kp = 0; kp < BK / 2; ++kp) {
                    float2 af[8];
#pragma unroll
                    for (int i = 0; i < 8; i++)
                        af[i] = __half22float2(*reinterpret_cast<const __half2*>(
                            Asb + (i * 16 + tr) * SSTRIDE + 2 * kp));
#pragma unroll
                    for (int jh = 0; jh < 2; jh++) {
                        float2 bf[8];
#pragma unroll
                        for (int j = 0; j < 8; j++)
                            bf[j] = __half22float2(*reinterpret_cast<const __half2*>(
                                Bsb + (tc * 16 + jh * 8 + j) * SSTRIDE + 2 * kp));
#pragma unroll
                        for (int i = 0; i < 8; i++)
#pragma unroll
                            for (int j = 0; j < 8; j++) {
                                acc[i][jh * 8 + j] =
                                    fmaf(af[i].x, bf[j].x, acc[i][jh * 8 + j]);
                                acc[i][jh * 8 + j] =
                                    fmaf(af[i].y, bf[j].y, acc[i][jh * 8 + j]);
                            }
                    }
                }
                __syncthreads();
            }

            // epilogue: 8 rows x 4 float4
#pragma unroll
            for (int i = 0; i < 8; i++) {
                const int r = m0 + i * 16 + tr;
                float* crow = C + (size_t)r * HIDD + n0 + tc * 16;
#pragma unroll
                for (int j4 = 0; j4 < 4; j4++) {
                    float4 v;
                    v.x = acc[i][j4 * 4 + 0];
                    v.y = acc[i][j4 * 4 + 1];
                    v.z = acc[i][j4 * 4 + 2];
                    v.w = acc[i][j4 * 4 + 3];
                    *reinterpret_cast<float4*>(crow + j4 * 4) = v;
                }
            }
        }
    }
}

// ---------------------------------------------------------------------------
extern "C" void kernel_launch(void* const* d_in, const int* in_sizes, int n_in,
                              void* d_out, int out_size) {
    const float* x      = (const float*)d_in[0];
    const float* W      = (const float*)d_in[1];
    const int*   nn_idx = (const int*)  d_in[2];
    const float* sim    = (const float*)d_in[3];
    float*       out    = (float*)d_out;

    __half* aggh = nullptr;
    __half* wh   = nullptr;
    cudaGetSymbolAddress((void**)&aggh, g_aggh);
    cudaGetSymbolAddress((void**)&wh,   g_Wh);

    cudaFuncSetAttribute(gemm_hybrid,
                         cudaFuncAttributeMaxDynamicSharedMemorySize, GEMM_SMEM);

    prep_kernel<<<8192 + 1024, 128>>>(x, nn_idx, sim, W);

    // 128 fma CTAs first (1/SM in wave 1), then 3584 tensor CTAs
    gemm_hybrid<<<FMA_CTAS + TENSOR_MBLK * 16, 128, GEMM_SMEM>>>(aggh, wh, out);
}

// round 8
// speedup vs baseline: 1.8248x; 1.8248x over previous
#include <cuda_runtime.h>
#include <cuda_fp16.h>
#include <cstdint>

// Problem constants
#define CTXD   512
#define HIDD   2048
#define NCELLS 4096      // 64*64
#define NBATCH 8
#define KNN    8
#define MTOT   (NBATCH * NCELLS)   // 32768

// Scratch (allowed: __device__ globals)
__device__ __half g_aggh[(size_t)MTOT * CTXD];  // 32 MB fp16 agg
__device__ __half g_Wh[(size_t)HIDD * CTXD];    // 2 MB  fp16 W^T (N rows, K cols)

// ---------------------------------------------------------------------------
// Kernel 1: fused prep.
//   blocks [0,512):    agg over an 8x8 cell tile (L1-friendly gather)
//   blocks [512,1536): W transpose -> fp16 (32x32 tiles)
// 128 threads per block.
// ---------------------------------------------------------------------------
#define AGG_BLOCKS 512
#define PREP_BLOCKS (AGG_BLOCKS + 1024)

__global__ __launch_bounds__(128) void prep_kernel(
    const float* __restrict__ x,
    const int*   __restrict__ nn_idx,
    const float* __restrict__ sim,
    const float* __restrict__ W)
{
    const int bid = blockIdx.x;
    const int t   = threadIdx.x;

    if (bid < AGG_BLOCKS) {
        // ---- agg: 8x8 cell tile, full 512-ctx width (t = float4 lane) ----
        const int b    = bid >> 6;          // batch
        const int tile = bid & 63;
        const int r0   = (tile >> 3) * 8;   // tile row origin
        const int c0   = (tile & 7) * 8;    // tile col origin

        __shared__ int   s_idx[64 * KNN];
        __shared__ float s_sim[64 * KNN];
        // load 64 cells' indices/sims (512 each), 4 per thread
#pragma unroll
        for (int i = 0; i < 4; i++) {
            const int slot = i * 128 + t;         // 0..511
            const int cell = slot >> 3;           // 0..63
            const int k    = slot & 7;
            const int n    = (r0 + (cell >> 3)) * 64 + (c0 + (cell & 7));
            s_idx[slot] = nn_idx[n * KNN + k];
            s_sim[slot] = sim[n * KNN + k];
        }
        __syncthreads();

        const float4* xb = reinterpret_cast<const float4*>(x) +
                           (size_t)b * NCELLS * (CTXD / 4);
        uint2* dst = reinterpret_cast<uint2*>(g_aggh);

#pragma unroll 2
        for (int cell = 0; cell < 64; cell++) {
            const int n = (r0 + (cell >> 3)) * 64 + (c0 + (cell & 7));
            float4 acc = make_float4(0.f, 0.f, 0.f, 0.f);
#pragma unroll
            for (int k = 0; k < KNN; k++) {
                const float  s = s_sim[cell * KNN + k];
                const float4 v = xb[(size_t)s_idx[cell * KNN + k] * (CTXD / 4) + t];
                acc.x = fmaf(s, v.x, acc.x);
                acc.y = fmaf(s, v.y, acc.y);
                acc.z = fmaf(s, v.z, acc.z);
                acc.w = fmaf(s, v.w, acc.w);
            }
            __half2 h0 = __float22half2_rn(make_float2(acc.x, acc.y));
            __half2 h1 = __float22half2_rn(make_float2(acc.z, acc.w));
            uint2 p;
            p.x = *reinterpret_cast<uint32_t*>(&h0);
            p.y = *reinterpret_cast<uint32_t*>(&h1);
            dst[((size_t)b * NCELLS + n) * (CTXD / 4) + t] = p;
        }
    } else {
        // ---- wtrans: Wt[n][k] = (half)W[k][n], 32x32 tile ----
        const int wb = bid - AGG_BLOCKS;     // 0..1023
        const int bx = wb & 63;              // HIDD/32
        const int by = wb >> 6;              // CTXD/32
        const int tx = t & 31;
        const int ty = t >> 5;               // 0..3

        __shared__ float tile[32][33];
#pragma unroll
        for (int i = 0; i < 8; i++)
            tile[ty + i * 4][tx] =
                W[(size_t)(by * 32 + ty + i * 4) * HIDD + bx * 32 + tx];
        __syncthreads();
#pragma unroll
        for (int i = 0; i < 8; i++)
            g_Wh[(size_t)(bx * 32 + ty + i * 4) * CTXD + by * 32 + tx] =
                __float2half(tile[tx][ty + i * 4]);
    }
}

// ---------------------------------------------------------------------------
// Kernel 2: fp16 mma.sync GEMM (round-6 proven), 128x128 CTA tile,
// 4 warps (warp tile 64x64), BK=64, 3-stage cp.async, ldmatrix, fp32 accum.
// ---------------------------------------------------------------------------
#define BM 128
#define BN 128
#define BK 64
#define NT (CTXD / BK)         // 8 k-chunks
#define SSTRIDE 72             // BK + 8 pad (halves)
#define TILE_H (128 * SSTRIDE)
#define STAGE_H (2 * TILE_H)
#define GEMM_SMEM (3 * STAGE_H * 2)   // 110592 bytes

__device__ __forceinline__ void cpasync16(uint32_t saddr, const void* g) {
    asm volatile("cp.async.cg.shared.global [%0], [%1], 16;\n" :: "r"(saddr), "l"(g));
}
__device__ __forceinline__ void ldsm_x4(uint32_t& r0, uint32_t& r1,
                                        uint32_t& r2, uint32_t& r3, uint32_t a) {
    asm volatile("ldmatrix.sync.aligned.m8n8.x4.shared.b16 {%0,%1,%2,%3},[%4];"
                 : "=r"(r0), "=r"(r1), "=r"(r2), "=r"(r3) : "r"(a));
}

__global__ __launch_bounds__(128, 2) void gemm_hmma(
    const __half* __restrict__ A,   // [MTOT][CTXD]
    const __half* __restrict__ B,   // [HIDD][CTXD]  (W^T)
    float*        __restrict__ C)   // [MTOT][HIDD]
{
    extern __shared__ __half sm[];

    const int tid  = threadIdx.x;
    const int lane = tid & 31;
    const int warp = tid >> 5;      // 0..3
    const int wm   = warp & 1;      // 64-row M half
    const int wn   = warp >> 1;     // 64-col N half
    const int g    = lane >> 2;     // 0..7
    const int t4   = lane & 3;      // 0..3

    const int m0 = blockIdx.y * BM;
    const int n0 = blockIdx.x * BN;

    float acc[4][8][4];
#pragma unroll
    for (int i = 0; i < 4; i++)
#pragma unroll
        for (int j = 0; j < 8; j++)
#pragma unroll
            for (int r = 0; r < 4; r++) acc[i][j][r] = 0.f;

    auto load_chunk = [&](int buf, int kt) {
        __half* Asb = sm + buf * STAGE_H;
        __half* Bsb = Asb + TILE_H;
        const __half* Ag = A + (size_t)m0 * CTXD + kt * BK;
        const __half* Bg = B + (size_t)n0 * CTXD + kt * BK;
#pragma unroll
        for (int i = 0; i < 8; i++) {
            int idx = i * 128 + tid;
            int row = idx >> 3;
            int c8  = (idx & 7) * 8;
            cpasync16((uint32_t)__cvta_generic_to_shared(Asb + row * SSTRIDE + c8),
                      Ag + (size_t)row * CTXD + c8);
        }
#pragma unroll
        for (int i = 0; i < 8; i++) {
            int idx = i * 128 + tid;
            int row = idx >> 3;
            int c8  = (idx & 7) * 8;
            cpasync16((uint32_t)__cvta_generic_to_shared(Bsb + row * SSTRIDE + c8),
                      Bg + (size_t)row * CTXD + c8);
        }
        asm volatile("cp.async.commit_group;\n");
    };

    load_chunk(0, 0);
    load_chunk(1, 1);

    const int a_r  = lane & 15;
    const int a_k  = (lane >> 4) * 8;
    const int b_r  = lane & 7;
    const int b_no = ((lane >> 3) >> 1) * 8;
    const int b_ko = ((lane >> 3) & 1) * 8;

    for (int kt = 0; kt < NT; ++kt) {
        if (kt + 1 < NT) asm volatile("cp.async.wait_group 1;\n");
        else             asm volatile("cp.async.wait_group 0;\n");
        __syncthreads();
        if (kt + 2 < NT) load_chunk((kt + 2) % 3, kt + 2);

        const __half* Asb = sm + (kt % 3) * STAGE_H;
        const __half* Bsb = Asb + TILE_H;

#pragma unroll
        for (int ks = 0; ks < 4; ++ks) {
            const int k0 = ks * 16;

            uint32_t af[4][4];
#pragma unroll
            for (int mi = 0; mi < 4; ++mi) {
                uint32_t a = (uint32_t)__cvta_generic_to_shared(
                    Asb + (wm * 64 + mi * 16 + a_r) * SSTRIDE + k0 + a_k);
                ldsm_x4(af[mi][0], af[mi][1], af[mi][2], af[mi][3], a);
            }
            uint32_t bf[8][2];
#pragma unroll
            for (int nj = 0; nj < 4; ++nj) {
                uint32_t a = (uint32_t)__cvta_generic_to_shared(
                    Bsb + (wn * 64 + nj * 16 + b_no + b_r) * SSTRIDE + k0 + b_ko);
                ldsm_x4(bf[2 * nj][0], bf[2 * nj][1],
                        bf[2 * nj + 1][0], bf[2 * nj + 1][1], a);
            }
#pragma unroll
            for (int mi = 0; mi < 4; ++mi)
#pragma unroll
                for (int ni = 0; ni < 8; ++ni) {
                    asm volatile(
                        "mma.sync.aligned.m16n8k16.row.col.f32.f16.f16.f32 "
                        "{%0,%1,%2,%3},{%4,%5,%6,%7},{%8,%9},{%0,%1,%2,%3};\n"
                        : "+f"(acc[mi][ni][0]), "+f"(acc[mi][ni][1]),
                          "+f"(acc[mi][ni][2]), "+f"(acc[mi][ni][3])
                        : "r"(af[mi][0]), "r"(af[mi][1]),
                          "r"(af[mi][2]), "r"(af[mi][3]),
                          "r"(bf[ni][0]), "r"(bf[ni][1]));
                }
        }
        __syncthreads();
    }

    // epilogue
#pragma unroll
    for (int mi = 0; mi < 4; ++mi) {
#pragma unroll
        for (int ni = 0; ni < 8; ++ni) {
            const int r = m0 + wm * 64 + mi * 16 + g;
            const int c = n0 + wn * 64 + ni * 8 + t4 * 2;
            float2 v0 = make_float2(acc[mi][ni][0], acc[mi][ni][1]);
            float2 v1 = make_float2(acc[mi][ni][2], acc[mi][ni][3]);
            *reinterpret_cast<float2*>(C + (size_t)r * HIDD + c)       = v0;
            *reinterpret_cast<float2*>(C + (size_t)(r + 8) * HIDD + c) = v1;
        }
    }
}

// ---------------------------------------------------------------------------
extern "C" void kernel_launch(void* const* d_in, const int* in_sizes, int n_in,
                              void* d_out, int out_size) {
    const float* x      = (const float*)d_in[0];
    const float* W      = (const float*)d_in[1];
    const int*   nn_idx = (const int*)  d_in[2];
    const float* sim    = (const float*)d_in[3];
    float*       out    = (float*)d_out;

    __half* aggh = nullptr;
    __half* wh   = nullptr;
    cudaGetSymbolAddress((void**)&aggh, g_aggh);
    cudaGetSymbolAddress((void**)&wh,   g_Wh);

    cudaFuncSetAttribute(gemm_hmma,
                         cudaFuncAttributeMaxDynamicSharedMemorySize, GEMM_SMEM);

    prep_kernel<<<PREP_BLOCKS, 128>>>(x, nn_idx, sim, W);

    dim3 g2(HIDD / BN, MTOT / BM);   // (16, 256)
    gemm_hmma<<<g2, 128, GEMM_SMEM>>>(aggh, wh, out);
}

// round 9
// speedup vs baseline: 2.0827x; 1.1413x over previous
#include <cuda_runtime.h>
#include <cuda_fp16.h>
#include <cstdint>

// Problem constants
#define CTXD   512
#define HIDD   2048
#define NCELLS 4096      // 64*64
#define NBATCH 8
#define KNN    8
#define MTOT   (NBATCH * NCELLS)   // 32768

// Scratch (allowed: __device__ globals)
__device__ __half g_aggh[(size_t)MTOT * CTXD];  // 32 MB fp16 agg
__device__ __half g_Wh[(size_t)HIDD * CTXD];    // 2 MB  fp16 W^T (N rows, K cols)

// ---------------------------------------------------------------------------
// Kernel 1: fused prep: agg (4 cells/block, high MLP) + W transpose->fp16
// grid: [0, 8192) agg blocks, [8192, 9216) wtrans blocks. 128 threads.
// ---------------------------------------------------------------------------
__global__ __launch_bounds__(128) void prep_kernel(
    const float* __restrict__ x,
    const int*   __restrict__ nn_idx,
    const float* __restrict__ sim,
    const float* __restrict__ W)
{
    const int bid = blockIdx.x;
    const int t   = threadIdx.x;

    if (bid < 8192) {
        const int n0 = (bid & 1023) * 4;
        const int b  = bid >> 10;

        __shared__ int   s_idx[4 * KNN];
        __shared__ float s_sim[4 * KNN];
        if (t < 4 * KNN) {
            s_idx[t] = nn_idx[n0 * KNN + t];
            s_sim[t] = sim[n0 * KNN + t];
        }
        __syncthreads();

        const float4* xb = reinterpret_cast<const float4*>(x) +
                           (size_t)b * NCELLS * (CTXD / 4);
        uint2* dst = reinterpret_cast<uint2*>(g_aggh);

#pragma unroll
        for (int c = 0; c < 4; c++) {
            float4 acc = make_float4(0.f, 0.f, 0.f, 0.f);
#pragma unroll
            for (int k = 0; k < KNN; k++) {
                const float  s = s_sim[c * KNN + k];
                const float4 v = xb[(size_t)s_idx[c * KNN + k] * (CTXD / 4) + t];
                acc.x = fmaf(s, v.x, acc.x);
                acc.y = fmaf(s, v.y, acc.y);
                acc.z = fmaf(s, v.z, acc.z);
                acc.w = fmaf(s, v.w, acc.w);
            }
            __half2 h0 = __float22half2_rn(make_float2(acc.x, acc.y));
            __half2 h1 = __float22half2_rn(make_float2(acc.z, acc.w));
            uint2 p;
            p.x = *reinterpret_cast<uint32_t*>(&h0);
            p.y = *reinterpret_cast<uint32_t*>(&h1);
            dst[((size_t)b * NCELLS + n0 + c) * (CTXD / 4) + t] = p;
        }
    } else {
        const int wb = bid - 8192;           // 0..1023
        const int bx = wb & 63;              // HIDD/32
        const int by = wb >> 6;              // CTXD/32
        const int tx = t & 31;
        const int ty = t >> 5;               // 0..3

        __shared__ float tile[32][33];
#pragma unroll
        for (int i = 0; i < 8; i++)
            tile[ty + i * 4][tx] =
                W[(size_t)(by * 32 + ty + i * 4) * HIDD + bx * 32 + tx];
        __syncthreads();
#pragma unroll
        for (int i = 0; i < 8; i++)
            g_Wh[(size_t)(bx * 32 + ty + i * 4) * CTXD + by * 32 + tx] =
                __float2half(tile[tx][ty + i * 4]);
    }
}

// ---------------------------------------------------------------------------
// Kernel 2: fp16 mma.sync GEMM, 128x128 CTA tile, 8 warps (warp tile 32x64),
// BK=64, 3-stage cp.async, ldmatrix, fp32 accum. 4 warps/SMSP at 2 CTA/SM.
// ---------------------------------------------------------------------------
#define BM 128
#define BN 128
#define BK 64
#define NT (CTXD / BK)         // 8 k-chunks
#define SSTRIDE 72             // BK + 8 pad (halves)
#define TILE_H (128 * SSTRIDE)
#define STAGE_H (2 * TILE_H)
#define GEMM_SMEM (3 * STAGE_H * 2)   // 110592 bytes

__device__ __forceinline__ void cpasync16(uint32_t saddr, const void* g) {
    asm volatile("cp.async.cg.shared.global [%0], [%1], 16;\n" :: "r"(saddr), "l"(g));
}
__device__ __forceinline__ void ldsm_x4(uint32_t& r0, uint32_t& r1,
                                        uint32_t& r2, uint32_t& r3, uint32_t a) {
    asm volatile("ldmatrix.sync.aligned.m8n8.x4.shared.b16 {%0,%1,%2,%3},[%4];"
                 : "=r"(r0), "=r"(r1), "=r"(r2), "=r"(r3) : "r"(a));
}

__global__ __launch_bounds__(256, 2) void gemm_hmma(
    const __half* __restrict__ A,   // [MTOT][CTXD]
    const __half* __restrict__ B,   // [HIDD][CTXD]  (W^T)
    float*        __restrict__ C)   // [MTOT][HIDD]
{
    extern __shared__ __half sm[];

    const int tid  = threadIdx.x;
    const int lane = tid & 31;
    const int warp = tid >> 5;      // 0..7
    const int wm   = warp & 3;      // 32-row M quarter
    const int wn   = warp >> 2;     // 64-col N half
    const int g    = lane >> 2;     // 0..7
    const int t4   = lane & 3;      // 0..3

    const int m0 = blockIdx.y * BM;
    const int n0 = blockIdx.x * BN;

    float acc[2][8][4];
#pragma unroll
    for (int i = 0; i < 2; i++)
#pragma unroll
        for (int j = 0; j < 8; j++)
#pragma unroll
            for (int r = 0; r < 4; r++) acc[i][j][r] = 0.f;

    // loader: 256 threads. A/B: 128 rows x 64 halves = 1024 x 16B each.
    auto load_chunk = [&](int buf, int kt) {
        __half* Asb = sm + buf * STAGE_H;
        __half* Bsb = Asb + TILE_H;
        const __half* Ag = A + (size_t)m0 * CTXD + kt * BK;
        const __half* Bg = B + (size_t)n0 * CTXD + kt * BK;
#pragma unroll
        for (int i = 0; i < 4; i++) {
            int idx = i * 256 + tid;
            int row = idx >> 3;
            int c8  = (idx & 7) * 8;
            cpasync16((uint32_t)__cvta_generic_to_shared(Asb + row * SSTRIDE + c8),
                      Ag + (size_t)row * CTXD + c8);
        }
#pragma unroll
        for (int i = 0; i < 4; i++) {
            int idx = i * 256 + tid;
            int row = idx >> 3;
            int c8  = (idx & 7) * 8;
            cpasync16((uint32_t)__cvta_generic_to_shared(Bsb + row * SSTRIDE + c8),
                      Bg + (size_t)row * CTXD + c8);
        }
        asm volatile("cp.async.commit_group;\n");
    };

    load_chunk(0, 0);
    load_chunk(1, 1);

    // ldmatrix lane address components
    const int a_r  = lane & 15;
    const int a_k  = (lane >> 4) * 8;
    const int b_r  = lane & 7;
    const int b_no = ((lane >> 3) >> 1) * 8;
    const int b_ko = ((lane >> 3) & 1) * 8;

    for (int kt = 0; kt < NT; ++kt) {
        if (kt + 1 < NT) asm volatile("cp.async.wait_group 1;\n");
        else             asm volatile("cp.async.wait_group 0;\n");
        __syncthreads();
        if (kt + 2 < NT) load_chunk((kt + 2) % 3, kt + 2);

        const __half* Asb = sm + (kt % 3) * STAGE_H;
        const __half* Bsb = Asb + TILE_H;

#pragma unroll
        for (int ks = 0; ks < 4; ++ks) {
            const int k0 = ks * 16;

            uint32_t af[2][4];
#pragma unroll
            for (int mi = 0; mi < 2; ++mi) {
                uint32_t a = (uint32_t)__cvta_generic_to_shared(
                    Asb + (wm * 32 + mi * 16 + a_r) * SSTRIDE + k0 + a_k);
                ldsm_x4(af[mi][0], af[mi][1], af[mi][2], af[mi][3], a);
            }
            uint32_t bf[8][2];
#pragma unroll
            for (int nj = 0; nj < 4; ++nj) {
                uint32_t a = (uint32_t)__cvta_generic_to_shared(
                    Bsb + (wn * 64 + nj * 16 + b_no + b_r) * SSTRIDE + k0 + b_ko);
                ldsm_x4(bf[2 * nj][0], bf[2 * nj][1],
                        bf[2 * nj + 1][0], bf[2 * nj + 1][1], a);
            }
#pragma unroll
            for (int mi = 0; mi < 2; ++mi)
#pragma unroll
                for (int ni = 0; ni < 8; ++ni) {
                    asm volatile(
                        "mma.sync.aligned.m16n8k16.row.col.f32.f16.f16.f32 "
                        "{%0,%1,%2,%3},{%4,%5,%6,%7},{%8,%9},{%0,%1,%2,%3};\n"
                        : "+f"(acc[mi][ni][0]), "+f"(acc[mi][ni][1]),
                          "+f"(acc[mi][ni][2]), "+f"(acc[mi][ni][3])
                        : "r"(af[mi][0]), "r"(af[mi][1]),
                          "r"(af[mi][2]), "r"(af[mi][3]),
                          "r"(bf[ni][0]), "r"(bf[ni][1]));
                }
        }
        __syncthreads();
    }

    // epilogue
#pragma unroll
    for (int mi = 0; mi < 2; ++mi) {
#pragma unroll
        for (int ni = 0; ni < 8; ++ni) {
            const int r = m0 + wm * 32 + mi * 16 + g;
            const int c = n0 + wn * 64 + ni * 8 + t4 * 2;
            float2 v0 = make_float2(acc[mi][ni][0], acc[mi][ni][1]);
            float2 v1 = make_float2(acc[mi][ni][2], acc[mi][ni][3]);
            *reinterpret_cast<float2*>(C + (size_t)r * HIDD + c)       = v0;
            *reinterpret_cast<float2*>(C + (size_t)(r + 8) * HIDD + c) = v1;
        }
    }
}

// ---------------------------------------------------------------------------
extern "C" void kernel_launch(void* const* d_in, const int* in_sizes, int n_in,
                              void* d_out, int out_size) {
    const float* x      = (const float*)d_in[0];
    const float* W      = (const float*)d_in[1];
    const int*   nn_idx = (const int*)  d_in[2];
    const float* sim    = (const float*)d_in[3];
    float*       out    = (float*)d_out;

    __half* aggh = nullptr;
    __half* wh   = nullptr;
    cudaGetSymbolAddress((void**)&aggh, g_aggh);
    cudaGetSymbolAddress((void**)&wh,   g_Wh);

    cudaFuncSetAttribute(gemm_hmma,
                         cudaFuncAttributeMaxDynamicSharedMemorySize, GEMM_SMEM);

    prep_kernel<<<8192 + 1024, 128>>>(x, nn_idx, sim, W);

    dim3 g2(HIDD / BN, MTOT / BM);   // (16, 256)
    gemm_hmma<<<g2, 256, GEMM_SMEM>>>(aggh, wh, out);
}